// round 8
// baseline (speedup 1.0000x reference)
#include <cuda_runtime.h>
#include <cstdint>

#define NB 8
#define NC 19
#define NH 512
#define NW 512
#define HW (NH * NW)            // 262144
#define NPIX (NB * HW)          // 2097152
#define NQUAD (HW / 4)          // 65536 pixel quads

// g_acc: [0..18] probs_sum_c, [19..37] inter_c, [38] focal [39] nll [40] slp [41] bnll
#define NACC 42

__device__ float g_acc[NACC];
__device__ int g_cnt[NC];
__device__ unsigned int g_ticket;
__device__ unsigned char g_diff[HW];

// ---------------------------------------------------------------------------
// Row-diff + target histogram with per-thread private smem bins.
#define DB 128
#define DG ((HW / 4) / DB)      // 512 blocks

__global__ __launch_bounds__(DB) void diff_kernel(const int* __restrict__ tgt) {
    __shared__ unsigned int s_h[DB][NC];
#pragma unroll
    for (int c = 0; c < NC; c++) s_h[threadIdx.x][c] = 0u;

    const int idx = blockIdx.x * DB + threadIdx.x;      // over HW/4
    const int h = idx >> 7;
    const bool interior = (h >= 1) && (h <= NH - 2);
    const int4* t4 = (const int4*)tgt;

    uchar4 d = make_uchar4(0, 0, 0, 0);
#pragma unroll
    for (int b = 0; b < NB; b++) {
        int base = b * (HW / 4) + idx;
        int4 m = __ldg(t4 + base);
        s_h[threadIdx.x][m.x]++;
        s_h[threadIdx.x][m.y]++;
        s_h[threadIdx.x][m.z]++;
        s_h[threadIdx.x][m.w]++;
        if (interior) {
            int4 a = __ldg(t4 + base - NW / 4);
            int4 q = __ldg(t4 + base + NW / 4);
            d.x |= (unsigned char)((a.x != m.x) | (a.x != q.x));
            d.y |= (unsigned char)((a.y != m.y) | (a.y != q.y));
            d.z |= (unsigned char)((a.z != m.z) | (a.z != q.z));
            d.w |= (unsigned char)((a.w != m.w) | (a.w != q.w));
        }
    }
    ((uchar4*)g_diff)[idx] = d;

    __syncthreads();
    if (threadIdx.x < NC) {
        unsigned int s = 0;
#pragma unroll 8
        for (int r = 0; r < DB; r++) s += s_h[r][threadIdx.x];
        atomicAdd(&g_cnt[threadIdx.x], (int)s);
    }
}

// ---------------------------------------------------------------------------
__device__ __forceinline__ float warp_sum(float v) {
#pragma unroll
    for (int o = 16; o; o >>= 1) v += __shfl_down_sync(0xffffffffu, v, o);
    return v;
}

// ---------------------------------------------------------------------------
// float4 pixel quads: 19 LDG.128 per iter, SEL-chain target select, per-warp
// shared inter bins, fused ticketed finalize.
#define MB 64
#define MAIN_BLOCKS (NQUAD / MB)   // 1024

__global__ __launch_bounds__(MB) void main_kernel(const float* __restrict__ in,
                                                  const int* __restrict__ tgt,
                                                  float* __restrict__ out) {
    __shared__ float s_int[2][NC];      // per-warp inter bins (2 warps)
    __shared__ float s_blk[NACC];
    __shared__ bool s_last;
    for (int t = threadIdx.x; t < NACC; t += MB) s_blk[t] = 0.0f;
    for (int t = threadIdx.x; t < 2 * NC; t += MB) ((float*)s_int)[t] = 0.0f;
    __syncthreads();

    const int tidg = blockIdx.x * MB + threadIdx.x;     // quad index
    const int wid = threadIdx.x >> 5;
    const int lane = threadIdx.x & 31;
    const int hw0 = 4 * tidg;
    const int h = hw0 >> 9;
    const int w0 = hw0 & (NW - 1);                      // multiple of 4

    // boundary flags for the 4 pixels (loop-invariant)
    float bm[4] = {0.f, 0.f, 0.f, 0.f};
    if (h >= 1 && h <= NH - 2) {
        unsigned char d0 = g_diff[hw0];
        unsigned char d1 = g_diff[hw0 + 1];
        unsigned char d2 = g_diff[hw0 + 2];
        unsigned char d3 = g_diff[hw0 + 3];
        if (w0 >= 1) bm[0] = (float)(g_diff[hw0 - 1] | d0 | d1);
        bm[1] = (float)(d0 | d1 | d2);
        bm[2] = (float)(d1 | d2 | d3);
        if (w0 + 3 <= NW - 2) bm[3] = (float)(d2 | d3 | g_diff[hw0 + 4]);
    }

    const float4* p = (const float4*)in + tidg;
    const int4* tp = (const int4*)tgt + tidg;

    float denom[NC];
#pragma unroll
    for (int c = 0; c < NC; c++) denom[c] = 0.0f;
    float a_focal = 0.0f, a_nll = 0.0f, a_slp = 0.0f, a_bnll = 0.0f;

#pragma unroll 1
    for (int b = 0; b < NB; b++) {
        const int4 tt = __ldg(tp);

        float4 e[NC];
        float sr0 = 0.f, sr1 = 0.f;                     // raw-logit grand sums
        float zx = 0.f, zy = 0.f, zz = 0.f, zw = 0.f;   // per-pixel partition fns
        float xt0 = 0.f, xt1 = 0.f, xt2 = 0.f, xt3 = 0.f;
#pragma unroll
        for (int c = 0; c < NC; c++) {
            float4 v = __ldg(p + (size_t)c * NQUAD);
            sr0 += v.x + v.y;
            sr1 += v.z + v.w;
            xt0 = (c == tt.x) ? v.x : xt0;
            xt1 = (c == tt.y) ? v.y : xt1;
            xt2 = (c == tt.z) ? v.z : xt2;
            xt3 = (c == tt.w) ? v.w : xt3;
            float ex = __expf(v.x);
            float ey = __expf(v.y);
            float ez = __expf(v.z);
            float ew = __expf(v.w);
            zx += ex; zy += ey; zz += ez; zw += ew;
            e[c].x = ex; e[c].y = ey; e[c].z = ez; e[c].w = ew;
        }

        const float i0 = __fdividef(1.0f, zx);
        const float i1 = __fdividef(1.0f, zy);
        const float i2 = __fdividef(1.0f, zz);
        const float i3 = __fdividef(1.0f, zw);
        const float l0 = __logf(zx);
        const float l1 = __logf(zy);
        const float l2 = __logf(zz);
        const float l3 = __logf(zw);
        const float n0 = l0 - xt0, n1 = l1 - xt1, n2 = l2 - xt2, n3 = l3 - xt3;
        const float p0 = __expf(xt0) * i0;
        const float p1 = __expf(xt1) * i1;
        const float p2 = __expf(xt2) * i2;
        const float p3 = __expf(xt3) * i3;

#pragma unroll
        for (int c = 0; c < NC; c++) {
            denom[c] = fmaf(e[c].x, i0, fmaf(e[c].y, i1,
                        fmaf(e[c].z, i2, fmaf(e[c].w, i3, denom[c]))));
        }

        const float o0 = 1.0f - p0, o1 = 1.0f - p1, o2 = 1.0f - p2, o3 = 1.0f - p3;
        a_focal += o0 * o0 * n0 + o1 * o1 * n1 + o2 * o2 * n2 + o3 * o3 * n3;
        a_nll += (n0 + n1) + (n2 + n3);
        a_slp += (sr0 + sr1) - (float)NC * ((l0 + l1) + (l2 + l3));
        a_bnll += n0 * bm[0] + n1 * bm[1] + n2 * bm[2] + n3 * bm[3];

        atomicAdd(&s_int[wid][tt.x], p0);
        atomicAdd(&s_int[wid][tt.y], p1);
        atomicAdd(&s_int[wid][tt.z], p2);
        atomicAdd(&s_int[wid][tt.w], p3);

        p += NC * NQUAD;
        tp += HW / 4;
    }

    // --- block reduction (2 warps) ---
#pragma unroll
    for (int c = 0; c < NC; c++) {
        float v = warp_sum(denom[c]);
        if (lane == 0) atomicAdd(&s_blk[c], v);
    }
    {
        float v = warp_sum(a_focal);
        if (lane == 0) atomicAdd(&s_blk[38], v);
        v = warp_sum(a_nll);
        if (lane == 0) atomicAdd(&s_blk[39], v);
        v = warp_sum(a_slp);
        if (lane == 0) atomicAdd(&s_blk[40], v);
        v = warp_sum(a_bnll);
        if (lane == 0) atomicAdd(&s_blk[41], v);
    }
    __syncthreads();

    if (threadIdx.x < NC) {
        atomicAdd(&g_acc[NC + threadIdx.x],
                  s_int[0][threadIdx.x] + s_int[1][threadIdx.x]);
    }
    if (threadIdx.x < NACC && (threadIdx.x < NC || threadIdx.x >= 38)) {
        atomicAdd(&g_acc[threadIdx.x], s_blk[threadIdx.x]);
    }

    // --- ticketed finalize + state cleanup (graph-replay safe) ---
    __threadfence();
    __syncthreads();
    if (threadIdx.x == 0)
        s_last = (atomicAdd(&g_ticket, 1u) == MAIN_BLOCKS - 1);
    __syncthreads();

    if (s_last && threadIdx.x < 32) {
        const float Ninv = 1.0f / (float)NPIX;
        float ps = (lane < NC) ? g_acc[lane] : 0.0f;
        float it = (lane < NC) ? g_acc[NC + lane] : 0.0f;
        float cn = (lane < NC) ? (float)g_cnt[lane] : 0.0f;
        float d = 0.0f;
        if (lane < NC) d = 1.0f - (2.0f * it + 1e-5f) / (ps + cn + 1e-5f);
        d = warp_sum(d);
        if (lane == 0) {
            float dice = d / (float)NC;
            float focal = g_acc[38] * Ninv;
            float nll_sum = g_acc[39];
            float slp_sum = g_acc[40];
            float ce = (0.9f * nll_sum - 0.1f * slp_sum / (float)NC) * Ninv;
            float boundary = (nll_sum + 0.5f * g_acc[41]) * Ninv;
            out[0] = focal;
            out[1] = dice;
            out[2] = ce;
            out[3] = boundary;
            out[4] = focal + dice + ce + boundary;
        }
        if (lane < NACC) g_acc[lane] = 0.0f;
        if (lane + 32 < NACC) g_acc[lane + 32] = 0.0f;
        if (lane < NC) g_cnt[lane] = 0;
        if (lane == 0) g_ticket = 0u;
    }
}

// ---------------------------------------------------------------------------
extern "C" void kernel_launch(void* const* d_in, const int* in_sizes, int n_in,
                              void* d_out, int out_size) {
    const float* inputs = (const float*)d_in[0];
    const int* targets = (const int*)d_in[1];
    float* out = (float*)d_out;

    diff_kernel<<<DG, DB>>>(targets);
    main_kernel<<<MAIN_BLOCKS, MB>>>(inputs, targets, out);
}

// round 9
// speedup vs baseline: 1.5202x; 1.5202x over previous
#include <cuda_runtime.h>
#include <cstdint>

#define NB 8
#define NC 19
#define NH 512
#define NW 512
#define HW (NH * NW)            // 262144
#define NPIX (NB * HW)          // 2097152
#define NPAIR (HW / 2)          // 131072 pixel pairs
#define NITERS (NPAIR * NB)     // 1048576 flattened pair-iterations

// g_acc: [0..18] probs_sum_c, [19..37] inter_c, [38] focal [39] nll [40] slp [41] bnll
#define NACC 42

__device__ float g_acc[NACC];
__device__ int g_cnt[NC];
__device__ unsigned int g_ticket;
__device__ unsigned char g_diff[HW];

// ---------------------------------------------------------------------------
// Row-diff + target histogram with per-thread private smem bins.
#define DB 128
#define DG ((HW / 4) / DB)      // 512 blocks

__global__ __launch_bounds__(DB) void diff_kernel(const int* __restrict__ tgt) {
    __shared__ unsigned int s_h[DB][NC];
#pragma unroll
    for (int c = 0; c < NC; c++) s_h[threadIdx.x][c] = 0u;

    const int idx = blockIdx.x * DB + threadIdx.x;      // over HW/4
    const int h = idx >> 7;
    const bool interior = (h >= 1) && (h <= NH - 2);
    const int4* t4 = (const int4*)tgt;

    uchar4 d = make_uchar4(0, 0, 0, 0);
#pragma unroll
    for (int b = 0; b < NB; b++) {
        int base = b * (HW / 4) + idx;
        int4 m = __ldg(t4 + base);
        s_h[threadIdx.x][m.x]++;
        s_h[threadIdx.x][m.y]++;
        s_h[threadIdx.x][m.z]++;
        s_h[threadIdx.x][m.w]++;
        if (interior) {
            int4 a = __ldg(t4 + base - NW / 4);
            int4 q = __ldg(t4 + base + NW / 4);
            d.x |= (unsigned char)((a.x != m.x) | (a.x != q.x));
            d.y |= (unsigned char)((a.y != m.y) | (a.y != q.y));
            d.z |= (unsigned char)((a.z != m.z) | (a.z != q.z));
            d.w |= (unsigned char)((a.w != m.w) | (a.w != q.w));
        }
    }
    ((uchar4*)g_diff)[idx] = d;

    __syncthreads();
    if (threadIdx.x < NC) {
        unsigned int s = 0;
#pragma unroll 8
        for (int r = 0; r < DB; r++) s += s_h[r][threadIdx.x];
        atomicAdd(&g_cnt[threadIdx.x], (int)s);
    }
}

// ---------------------------------------------------------------------------
__device__ __forceinline__ float warp_sum(float v) {
#pragma unroll
    for (int o = 16; o; o >>= 1) v += __shfl_down_sync(0xffffffffu, v, o);
    return v;
}

// ---------------------------------------------------------------------------
// Persistent single-wave grid: 296 CTAs (2/SM), flattened (pair, batch) space.
#define MAIN_BLOCKS 296
#define NTH (MAIN_BLOCKS * 256)     // 75776 threads

__global__ __launch_bounds__(256, 2) void main_kernel(const float* __restrict__ in,
                                                      const int* __restrict__ tgt,
                                                      float* __restrict__ out) {
    __shared__ float s_int[8][NC];      // per-warp inter bins
    __shared__ float s_blk[NACC];
    __shared__ bool s_last;
    {
        int t = threadIdx.x;
        if (t < NACC) s_blk[t] = 0.0f;
        if (t < 8 * NC) ((float*)s_int)[t] = 0.0f;
    }
    __syncthreads();

    const int tid = blockIdx.x * 256 + threadIdx.x;
    const int wid = threadIdx.x >> 5;
    const int lane = threadIdx.x & 31;

    const float2* in2 = (const float2*)in;
    const int2* tgt2 = (const int2*)tgt;

    float denom[NC];
#pragma unroll
    for (int c = 0; c < NC; c++) denom[c] = 0.0f;
    float a_focal = 0.0f, a_nll = 0.0f, a_slp = 0.0f, a_bnll = 0.0f;

#pragma unroll 1
    for (int idx = tid; idx < NITERS; idx += NTH) {
        const int pair = idx & (NPAIR - 1);
        const int b = idx >> 17;               // NPAIR == 2^17

        // boundary flags for the 2 pixels (g_diff is L1/L2-resident, 256 KB)
        const int hw0 = 2 * pair;
        const int h = hw0 >> 9;
        const int w0 = hw0 & (NW - 1);
        float bm0 = 0.0f, bm1 = 0.0f;
        if (h >= 1 && h <= NH - 2) {
            unsigned char dm = g_diff[hw0];
            unsigned char dp = g_diff[hw0 + 1];
            if (w0 >= 1) bm0 = (float)(g_diff[hw0 - 1] | dm | dp);
            if (w0 + 1 <= NW - 2) bm1 = (float)(dm | dp | g_diff[hw0 + 2]);
        }

        const int2 tt = __ldg(tgt2 + b * (HW / 2) + pair);
        const int t0 = tt.x, t1 = tt.y;
        const float2* base = in2 + (size_t)b * (NC * (HW / 2)) + pair;

        // load 19 float2 (front-batched), SEL-chain target select
        float2 x[NC];
        float xt0 = 0.0f, xt1 = 0.0f;
#pragma unroll
        for (int c = 0; c < NC; c++) {
            x[c] = __ldg(base + (size_t)c * (HW / 2));
            xt0 = (c == t0) ? x[c].x : xt0;
            xt1 = (c == t1) ? x[c].y : xt1;
        }

        // raw-logit sums (2 chains per pixel)
        float sA0 = 0.f, sB0 = 0.f, sA1 = 0.f, sB1 = 0.f;
#pragma unroll
        for (int c = 0; c < NC; c++) {
            if (c & 1) { sB0 += x[c].x; sB1 += x[c].y; }
            else       { sA0 += x[c].x; sA1 += x[c].y; }
        }
        const float sumx0 = sA0 + sB0, sumx1 = sA1 + sB1;

        // exponentials + partition functions
        float zA0 = 0.f, zB0 = 0.f, zA1 = 0.f, zB1 = 0.f;
#pragma unroll
        for (int c = 0; c < NC; c++) {
            x[c].x = __expf(x[c].x);
            x[c].y = __expf(x[c].y);
            if (c & 1) { zB0 += x[c].x; zB1 += x[c].y; }
            else       { zA0 += x[c].x; zA1 += x[c].y; }
        }
        const float Z0 = zA0 + zB0, Z1 = zA1 + zB1;

        const float invZ0 = __fdividef(1.0f, Z0);
        const float invZ1 = __fdividef(1.0f, Z1);
        const float logZ0 = __logf(Z0);
        const float logZ1 = __logf(Z1);
        const float nll0 = logZ0 - xt0;
        const float nll1 = logZ1 - xt1;
        const float pt0 = __expf(xt0) * invZ0;
        const float pt1 = __expf(xt1) * invZ1;

#pragma unroll
        for (int c = 0; c < NC; c++) {
            denom[c] = fmaf(x[c].x, invZ0, fmaf(x[c].y, invZ1, denom[c]));
        }

        const float om0 = 1.0f - pt0, om1 = 1.0f - pt1;
        a_focal = fmaf(om0 * om0, nll0, fmaf(om1 * om1, nll1, a_focal));
        a_nll += nll0 + nll1;
        a_slp += (sumx0 + sumx1) - (float)NC * (logZ0 + logZ1);
        a_bnll = fmaf(nll0, bm0, fmaf(nll1, bm1, a_bnll));

        atomicAdd(&s_int[wid][t0], pt0);
        atomicAdd(&s_int[wid][t1], pt1);
    }

    // --- block reduction ---
#pragma unroll
    for (int c = 0; c < NC; c++) {
        float v = warp_sum(denom[c]);
        if (lane == 0) atomicAdd(&s_blk[c], v);
    }
    {
        float v = warp_sum(a_focal);
        if (lane == 0) atomicAdd(&s_blk[38], v);
        v = warp_sum(a_nll);
        if (lane == 0) atomicAdd(&s_blk[39], v);
        v = warp_sum(a_slp);
        if (lane == 0) atomicAdd(&s_blk[40], v);
        v = warp_sum(a_bnll);
        if (lane == 0) atomicAdd(&s_blk[41], v);
    }
    __syncthreads();

    if (threadIdx.x < NC) {
        float vi = 0.0f;
#pragma unroll
        for (int wsel = 0; wsel < 8; wsel++) vi += s_int[wsel][threadIdx.x];
        atomicAdd(&g_acc[NC + threadIdx.x], vi);
    }
    if (threadIdx.x < NACC && (threadIdx.x < NC || threadIdx.x >= 38)) {
        atomicAdd(&g_acc[threadIdx.x], s_blk[threadIdx.x]);
    }

    // --- ticketed finalize + state cleanup (graph-replay safe) ---
    __threadfence();
    __syncthreads();
    if (threadIdx.x == 0)
        s_last = (atomicAdd(&g_ticket, 1u) == MAIN_BLOCKS - 1);
    __syncthreads();

    if (s_last && threadIdx.x < 32) {
        const float Ninv = 1.0f / (float)NPIX;
        float ps = (lane < NC) ? g_acc[lane] : 0.0f;
        float it = (lane < NC) ? g_acc[NC + lane] : 0.0f;
        float cn = (lane < NC) ? (float)g_cnt[lane] : 0.0f;
        float d = 0.0f;
        if (lane < NC) d = 1.0f - (2.0f * it + 1e-5f) / (ps + cn + 1e-5f);
        d = warp_sum(d);
        if (lane == 0) {
            float dice = d / (float)NC;
            float focal = g_acc[38] * Ninv;
            float nll_sum = g_acc[39];
            float slp_sum = g_acc[40];
            float ce = (0.9f * nll_sum - 0.1f * slp_sum / (float)NC) * Ninv;
            float boundary = (nll_sum + 0.5f * g_acc[41]) * Ninv;
            out[0] = focal;
            out[1] = dice;
            out[2] = ce;
            out[3] = boundary;
            out[4] = focal + dice + ce + boundary;
        }
        if (lane < NACC) g_acc[lane] = 0.0f;
        if (lane + 32 < NACC) g_acc[lane + 32] = 0.0f;
        if (lane < NC) g_cnt[lane] = 0;
        if (lane == 0) g_ticket = 0u;
    }
}

// ---------------------------------------------------------------------------
extern "C" void kernel_launch(void* const* d_in, const int* in_sizes, int n_in,
                              void* d_out, int out_size) {
    const float* inputs = (const float*)d_in[0];
    const int* targets = (const int*)d_in[1];
    float* out = (float*)d_out;

    diff_kernel<<<DG, DB>>>(targets);
    main_kernel<<<MAIN_BLOCKS, 256>>>(inputs, targets, out);
}